// round 9
// baseline (speedup 1.0000x reference)
#include <cuda_runtime.h>
#include <cuda_bf16.h>
#include <cstdint>

// ---------------------------------------------------------------------------
// NetVLAD GB300 round 8: single-pass TF32 mma.sync pool GEMM
// N=32, C=1024, D=128, K=64, S=784 (13 tiles of 64), OUT=1024
// ---------------------------------------------------------------------------

__device__ float g_wt[131072];            // Wpool pre-rounded to tf32, [d][c]
__device__ float g_vladraw[32 * 8192];
__device__ float g_vlad  [32 * 8192];
__device__ float g_sasum [32 * 64];
__device__ float g_proj  [32 * 1024];

#define FMA2(acc, a, b) \
    asm("fma.rn.f32x2 %0, %1, %2, %0;" : "+l"(acc) : "l"(a), "l"(b))
#define DUP2(d, s) \
    asm("mov.b64 %0, {%1, %1};" : "=l"(d) : "f"(s))
#define UNPK(lo, hi, s) \
    asm("mov.b64 {%0, %1}, %2;" : "=f"(lo), "=f"(hi) : "l"(s))

__device__ __forceinline__ unsigned cvt_tf32(float v) {
    unsigned u;
    asm("cvt.rna.tf32.f32 %0, %1;" : "=r"(u) : "f"(v));
    return u;
}
__device__ __forceinline__ void mma_tf32(float* c, const unsigned* a, const unsigned* b) {
    asm volatile(
        "mma.sync.aligned.m16n8k8.row.col.f32.tf32.tf32.f32 "
        "{%0,%1,%2,%3}, {%4,%5,%6,%7}, {%8,%9}, {%0,%1,%2,%3};"
        : "+f"(c[0]), "+f"(c[1]), "+f"(c[2]), "+f"(c[3])
        : "r"(a[0]), "r"(a[1]), "r"(a[2]), "r"(a[3]), "r"(b[0]), "r"(b[1]));
}

// ---------------------------------------------------------------------------
__global__ void kW(const float* __restrict__ Wpool) {
    int idx = blockIdx.x * 256 + threadIdx.x;
    if (idx >= 131072) return;
    g_wt[idx] = __uint_as_float(cvt_tf32(Wpool[idx]));
}

__global__ void kZ() {
    int idx = blockIdx.x * 256 + threadIdx.x;
    if (idx < 262144) g_vladraw[idx] = 0.f;
    if (idx < 2048)   g_sasum[idx] = 0.f;
    if (idx < 32768)  g_proj[idx] = 0.f;
}

// ---------------------------------------------------------------------------
// kA: TF32 mma pool GEMM (128d x 64s) + bias + col L2 norm + logits + softmax
//     + fused vlad partial.  grid (13 s-tiles, 32 n), 256 thr, smem 78592 B
// phase1 floats: WT@256 [128][68] fp32(tf32) -> ends 8960
//                XT@8960 [64][72] fp32(tf32) -> ends 13568
// phase2 floats: XF_A@256 [128][68] (acc -> WconvT -> saT)
//                XF_B@8960 [64 s][132 d] | EP3@17408 [64][34] | EP4@19584 [64]
// ---------------------------------------------------------------------------
__global__ void __launch_bounds__(256, 2) kA(const float* __restrict__ x,
                                             const float* __restrict__ bpool,
                                             const float* __restrict__ Wconv,
                                             const float* __restrict__ bconv) {
    extern __shared__ char smc[];
    float* smf = (float*)smc;

    const int tid = threadIdx.x, lane = tid & 31, wid = tid >> 5;
    const int n = blockIdx.y;
    const int s0 = blockIdx.x * 64;
    const bool fullv = (blockIdx.x < 12);

    const int WT = 256, XT = 8960;
    const int XF_A = 256, XF_B = 8960, EP3 = 17408, EP4 = 19584;

    const float* xn = x + (size_t)n * 1024 * 784;
    const int xc = tid >> 2, xs = (tid & 3) * 16;     // X staging: c row, s sub
    const int wrow = tid >> 1, wcol = (tid & 1) * 32; // W staging

    const int wd = wid & 3, ws = wid >> 2;
    const int md0 = wd * 32, ns0 = ws * 32;

    // fragment base addresses (float offsets)
    const int aB = WT + (md0 + (lane >> 2)) * 68 + (lane & 3);
    const int bB = XT + (lane & 3) * 72 + ns0 + (lane >> 2);

    float acc[2][4][4];
#pragma unroll
    for (int mt = 0; mt < 2; mt++)
#pragma unroll
        for (int nf = 0; nf < 4; nf++)
#pragma unroll
            for (int u = 0; u < 4; u++) acc[mt][nf][u] = 0.f;

    for (int q = 0; q < 16; q++) {
        if (q) __syncthreads();
        // ---- W chunk: 32 fp32 per thread, already tf32-rounded ----
        {
            const float4* pw = (const float4*)(g_wt + (size_t)wrow * 1024 + q * 64 + wcol);
            float4 w[8];
#pragma unroll
            for (int u = 0; u < 8; u++) w[u] = pw[u];
            float4* dw = (float4*)(smf + WT + wrow * 68 + wcol);
#pragma unroll
            for (int u = 0; u < 8; u++) dw[u] = w[u];
        }
        // ---- X chunk: one c-row x 16 s, round to tf32 ----
        {
            const float* p0 = xn + (size_t)(q * 64 + xc) * 784 + s0 + xs;
            float t[16];
            if (fullv) {
#pragma unroll
                for (int u = 0; u < 4; u++) {
                    float4 a = ((const float4*)p0)[u];
                    t[u * 4] = a.x; t[u * 4 + 1] = a.y;
                    t[u * 4 + 2] = a.z; t[u * 4 + 3] = a.w;
                }
            } else {
#pragma unroll
                for (int i = 0; i < 16; i++)
                    t[i] = ((s0 + xs + i) < 784) ? p0[i] : 0.f;
            }
            uint4* dx = (uint4*)(smf + XT + xc * 72 + xs);
#pragma unroll
            for (int u = 0; u < 4; u++) {
                uint4 o;
                o.x = cvt_tf32(t[u * 4 + 0]);
                o.y = cvt_tf32(t[u * 4 + 1]);
                o.z = cvt_tf32(t[u * 4 + 2]);
                o.w = cvt_tf32(t[u * 4 + 3]);
                dx[u] = o;
            }
        }
        __syncthreads();
        // ---- mma: k = 64 in 8 k-steps of 8 ----
#pragma unroll
        for (int ks = 0; ks < 8; ks++) {
            const int ka = aB + ks * 8;
            const int kb = bB + ks * 576;   // 8 rows * 72
            unsigned a[2][4], b[4][2];
#pragma unroll
            for (int mt = 0; mt < 2; mt++) {
                a[mt][0] = __float_as_uint(smf[ka + mt * 1088]);
                a[mt][1] = __float_as_uint(smf[ka + mt * 1088 + 544]);
                a[mt][2] = __float_as_uint(smf[ka + mt * 1088 + 4]);
                a[mt][3] = __float_as_uint(smf[ka + mt * 1088 + 548]);
            }
#pragma unroll
            for (int nf = 0; nf < 4; nf++) {
                b[nf][0] = __float_as_uint(smf[kb + nf * 8]);
                b[nf][1] = __float_as_uint(smf[kb + nf * 8 + 288]);  // +4 rows
            }
#pragma unroll
            for (int mt = 0; mt < 2; mt++)
#pragma unroll
                for (int nf = 0; nf < 4; nf++)
                    mma_tf32(acc[mt][nf], a[mt], b[nf]);
        }
    }
    __syncthreads();

    // ---- acc -> XF_A[d][s] (+bias) ----
    {
        const int r0w = lane >> 2, cq = (lane & 3) * 2;
#pragma unroll
        for (int mt = 0; mt < 2; mt++) {
            int d = md0 + mt * 16 + r0w;
            float b0 = __ldg(&bpool[d]);
            float b8 = __ldg(&bpool[d + 8]);
#pragma unroll
            for (int nf = 0; nf < 4; nf++) {
                int s = ns0 + nf * 8 + cq;
                smf[XF_A + d * 68 + s]           = acc[mt][nf][0] + b0;
                smf[XF_A + d * 68 + s + 1]       = acc[mt][nf][1] + b0;
                smf[XF_A + (d + 8) * 68 + s]     = acc[mt][nf][2] + b8;
                smf[XF_A + (d + 8) * 68 + s + 1] = acc[mt][nf][3] + b8;
            }
        }
    }
    __syncthreads();

    // ---- column L2 norm over d ----
    if (tid < 64) {
        float s = 0.f;
#pragma unroll 8
        for (int d = 0; d < 128; d++) {
            float v = smf[XF_A + d * 68 + tid];
            s += v * v;
        }
        smf[EP4 + tid] = ((s0 + tid) < 784) ? 1.f / fmaxf(sqrtf(s), 1e-12f) : 0.f;
    }
    __syncthreads();

    // ---- build normalized XF_B[s][d] ----
    {
        const int row = tid & 127, hs = tid >> 7;
#pragma unroll
        for (int g = 0; g < 8; g++) {
            int s4 = hs * 32 + g * 4;
            float4 v = *(const float4*)&smf[XF_A + row * 68 + s4];
            float4 m = *(const float4*)&smf[EP4 + s4];
            smf[XF_B + (s4 + 0) * 132 + row] = v.x * m.x;
            smf[XF_B + (s4 + 1) * 132 + row] = v.y * m.y;
            smf[XF_B + (s4 + 2) * 132 + row] = v.z * m.z;
            smf[XF_B + (s4 + 3) * 132 + row] = v.w * m.w;
        }
    }
    __syncthreads();

    // ---- stage WconvT[d][k] into XF_A region ----
    {
        int kr = tid & 63, dq = tid >> 6;
#pragma unroll
        for (int u = 0; u < 8; u++) {
            float4 w = *(const float4*)&Wconv[kr * 128 + dq * 32 + u * 4];
            smf[XF_A + (dq * 32 + u * 4 + 0) * 68 + kr] = w.x;
            smf[XF_A + (dq * 32 + u * 4 + 1) * 68 + kr] = w.y;
            smf[XF_A + (dq * 32 + u * 4 + 2) * 68 + kr] = w.z;
            smf[XF_A + (dq * 32 + u * 4 + 3) * 68 + kr] = w.w;
        }
    }
    __syncthreads();

    // ---- logits: kg -> 8 k, sc -> s pair ----
    const int kg = tid & 7;
    const int sc = tid >> 3;
    unsigned long long a2[4][2];
#pragma unroll
    for (int p = 0; p < 4; p++) { a2[p][0] = 0ull; a2[p][1] = 0ull; }
    for (int d = 0; d < 128; d++) {
        ulonglong2 w0 = *(const ulonglong2*)&smf[XF_A + d * 68 + kg * 8];
        ulonglong2 w1 = *(const ulonglong2*)&smf[XF_A + d * 68 + kg * 8 + 4];
        float x0 = smf[XF_B + (2 * sc) * 132 + d];
        float x1 = smf[XF_B + (2 * sc + 1) * 132 + d];
        unsigned long long xd0, xd1;
        DUP2(xd0, x0); DUP2(xd1, x1);
        FMA2(a2[0][0], w0.x, xd0); FMA2(a2[0][1], w0.x, xd1);
        FMA2(a2[1][0], w0.y, xd0); FMA2(a2[1][1], w0.y, xd1);
        FMA2(a2[2][0], w1.x, xd0); FMA2(a2[2][1], w1.x, xd1);
        FMA2(a2[3][0], w1.y, xd0); FMA2(a2[3][1], w1.y, xd1);
    }
    float l[8][2];
#pragma unroll
    for (int p = 0; p < 4; p++) {
        UNPK(l[2 * p][0], l[2 * p + 1][0], a2[p][0]);
        UNPK(l[2 * p][1], l[2 * p + 1][1], a2[p][1]);
    }
#pragma unroll
    for (int i = 0; i < 8; i++) {
        float b = bconv[kg * 8 + i];
        l[i][0] += b; l[i][1] += b;
    }

    // ---- softmax over K per column ----
#pragma unroll
    for (int j = 0; j < 2; j++) {
        float m = l[0][j];
#pragma unroll
        for (int i = 1; i < 8; i++) m = fmaxf(m, l[i][j]);
        smf[EP3 + (2 * sc + j) * 17 + kg] = m;
    }
    __syncthreads();
    if (tid < 64) {
        float m = smf[EP3 + tid * 17];
#pragma unroll
        for (int t = 1; t < 8; t++) m = fmaxf(m, smf[EP3 + tid * 17 + t]);
        smf[EP4 + tid] = m;
    }
    __syncthreads();
    float e[8][2];
#pragma unroll
    for (int j = 0; j < 2; j++) {
        float M = smf[EP4 + 2 * sc + j];
        float ssum = 0.f;
#pragma unroll
        for (int i = 0; i < 8; i++) { e[i][j] = __expf(l[i][j] - M); ssum += e[i][j]; }
        smf[EP3 + (2 * sc + j) * 17 + kg] = ssum;
    }
    __syncthreads();
    if (tid < 64) {
        float t = 0.f;
#pragma unroll
        for (int qq = 0; qq < 8; qq++) t += smf[EP3 + tid * 17 + qq];
        smf[EP4 + tid] = 1.f / t;
    }
    __syncthreads();

    // ---- saT[s][k] into XF_A + sasum partials ----
    float ps[8];
#pragma unroll
    for (int i = 0; i < 8; i++) ps[i] = 0.f;
#pragma unroll
    for (int j = 0; j < 2; j++) {
        int sl = 2 * sc + j;
        float r = ((s0 + sl) < 784) ? smf[EP4 + sl] : 0.f;
#pragma unroll
        for (int i = 0; i < 8; i++) {
            float val = e[i][j] * r;
            smf[XF_A + sl * 68 + kg * 8 + i] = val;
            ps[i] += val;
        }
    }
    __syncthreads();
#pragma unroll
    for (int i = 0; i < 8; i++)
        smf[EP3 + (kg * 8 + i) * 34 + sc] = ps[i];
    __syncthreads();
    if (tid < 64) {
        float s = 0.f;
#pragma unroll
        for (int c = 0; c < 32; c++) s += smf[EP3 + tid * 34 + c];
        atomicAdd(&g_sasum[n * 64 + tid], s);
    }

    // ---- vlad partial: saT @ XF_B -> g_vladraw ----
    const int tk = tid >> 4;
    const int dg = tid & 15;
    unsigned long long vacc[4][4];
#pragma unroll
    for (int qk = 0; qk < 4; qk++)
#pragma unroll
        for (int p = 0; p < 4; p++) vacc[qk][p] = 0ull;
    for (int s = 0; s < 64; s++) {
        float4 sv = *(const float4*)&smf[XF_A + s * 68 + tk * 4];
        ulonglong2 xa = *(const ulonglong2*)&smf[XF_B + s * 132 + dg * 8];
        ulonglong2 xb = *(const ulonglong2*)&smf[XF_B + s * 132 + dg * 8 + 4];
        unsigned long long d0, d1, d2, d3;
        DUP2(d0, sv.x); DUP2(d1, sv.y); DUP2(d2, sv.z); DUP2(d3, sv.w);
        FMA2(vacc[0][0], d0, xa.x); FMA2(vacc[0][1], d0, xa.y);
        FMA2(vacc[0][2], d0, xb.x); FMA2(vacc[0][3], d0, xb.y);
        FMA2(vacc[1][0], d1, xa.x); FMA2(vacc[1][1], d1, xa.y);
        FMA2(vacc[1][2], d1, xb.x); FMA2(vacc[1][3], d1, xb.y);
        FMA2(vacc[2][0], d2, xa.x); FMA2(vacc[2][1], d2, xa.y);
        FMA2(vacc[2][2], d2, xb.x); FMA2(vacc[2][3], d2, xb.y);
        FMA2(vacc[3][0], d3, xa.x); FMA2(vacc[3][1], d3, xa.y);
        FMA2(vacc[3][2], d3, xb.x); FMA2(vacc[3][3], d3, xb.y);
    }
    float* vr = g_vladraw + (size_t)n * 8192;
#pragma unroll
    for (int qk = 0; qk < 4; qk++)
#pragma unroll
        for (int p = 0; p < 4; p++) {
            float lo, hi;
            UNPK(lo, hi, vacc[qk][p]);
            int base = (tk * 4 + qk) * 128 + dg * 8 + p * 2;
            atomicAdd(&vr[base], lo);
            atomicAdd(&vr[base + 1], hi);
        }
}

// ---------------------------------------------------------------------------
// kBfin: vlad = vladraw - centroids*sasum, intra-norm over K
// grid (4 d-tiles, 32 n), 256 thr = 32 d x 8 k-groups
// ---------------------------------------------------------------------------
__global__ void __launch_bounds__(256) kBfin(const float* __restrict__ centroids) {
    __shared__ float ssm[64];
    __shared__ float red[8][33];
    const int dt = blockIdx.x, n = blockIdx.y, tid = threadIdx.x;
    const int dl = tid & 31, kg = tid >> 5;
    const int d = dt * 32 + dl;
    if (tid < 64) ssm[tid] = g_sasum[n * 64 + tid];
    __syncthreads();
    const float* vr = g_vladraw + (size_t)n * 8192;
    float v[8], sq = 0.f;
#pragma unroll
    for (int j = 0; j < 8; j++) {
        int k = kg * 8 + j;
        float val = vr[k * 128 + d] - centroids[k * 128 + d] * ssm[k];
        v[j] = val;
        sq += val * val;
    }
    red[kg][dl] = sq;
    __syncthreads();
    float tot = 0.f;
#pragma unroll
    for (int t = 0; t < 8; t++) tot += red[t][dl];
    float inv = 1.f / fmaxf(sqrtf(tot), 1e-12f);
    float* vo = g_vlad + (size_t)n * 8192;
#pragma unroll
    for (int j = 0; j < 8; j++)
        vo[(kg * 8 + j) * 128 + d] = v[j] * inv;
}

// ---------------------------------------------------------------------------
// kC: proj += vlad @ Wproj^T.  grid (8 o-tiles of 128, 16 j-splits of 512)
// ---------------------------------------------------------------------------
__global__ void __launch_bounds__(256) kC(const float* __restrict__ Wproj) {
    __shared__ float wT[32 * 132];   // [j][o]
    __shared__ float vT[32 * 36];    // [j][n]
    const int tid = threadIdx.x;
    const int ob = blockIdx.x * 128;
    const int jb = blockIdx.y * 512;
    const int og = tid >> 4;
    const int ng = tid & 15;

    unsigned long long acc[8];
#pragma unroll
    for (int i = 0; i < 8; i++) acc[i] = 0ull;

    const int wo = tid >> 1, wj = (tid & 1) * 16;
    const int vn = tid >> 3, vj = (tid & 7) * 4;

    for (int jt = 0; jt < 512; jt += 32) {
        __syncthreads();
        {
            const float* wr = &Wproj[(size_t)(ob + wo) * 8192 + jb + jt + wj];
#pragma unroll
            for (int u = 0; u < 4; u++) {
                float4 w = *(const float4*)&wr[u * 4];
                wT[(wj + u * 4 + 0) * 132 + wo] = w.x;
                wT[(wj + u * 4 + 1) * 132 + wo] = w.y;
                wT[(wj + u * 4 + 2) * 132 + wo] = w.z;
                wT[(wj + u * 4 + 3) * 132 + wo] = w.w;
            }
            float4 v = *(const float4*)&g_vlad[(size_t)vn * 8192 + jb + jt + vj];
            vT[(vj + 0) * 36 + vn] = v.x;
            vT[(vj + 1) * 36 + vn] = v.y;
            vT[(vj + 2) * 36 + vn] = v.z;
            vT[(vj + 3) * 36 + vn] = v.w;
        }
        __syncthreads();
#pragma unroll
        for (int j = 0; j < 32; j++) {
            float4 w0 = *(const float4*)&wT[j * 132 + og * 8];
            float4 w1 = *(const float4*)&wT[j * 132 + og * 8 + 4];
            unsigned long long vp = *(const unsigned long long*)&vT[j * 36 + ng * 2];
            unsigned long long wdr[8];
            DUP2(wdr[0], w0.x); DUP2(wdr[1], w0.y); DUP2(wdr[2], w0.z); DUP2(wdr[3], w0.w);
            DUP2(wdr[4], w1.x); DUP2(wdr[5], w1.y); DUP2(wdr[6], w1.z); DUP2(wdr[7], w1.w);
#pragma unroll
            for (int i = 0; i < 8; i++) FMA2(acc[i], wdr[i], vp);
        }
    }
#pragma unroll
    for (int i = 0; i < 8; i++) {
        float lo, hi;
        UNPK(lo, hi, acc[i]);
        int o = ob + og * 8 + i;
        atomicAdd(&g_proj[(ng * 2 + 0) * 1024 + o], lo);
        atomicAdd(&g_proj[(ng * 2 + 1) * 1024 + o], hi);
    }
}

// ---------------------------------------------------------------------------
__global__ void __launch_bounds__(256) kD(const float* __restrict__ bproj,
                                          float* __restrict__ out) {
    __shared__ float wr[8];
    __shared__ float inv_s;
    const int n = blockIdx.x, tid = threadIdx.x;
    float v[4]; float ps = 0.f;
#pragma unroll
    for (int r = 0; r < 4; r++) {
        int o = r * 256 + tid;
        v[r] = g_proj[n * 1024 + o] + bproj[o];
        ps += v[r] * v[r];
    }
#pragma unroll
    for (int off = 16; off; off >>= 1)
        ps += __shfl_xor_sync(0xffffffffu, ps, off);
    if ((tid & 31) == 0) wr[tid >> 5] = ps;
    __syncthreads();
    if (tid == 0) {
        float s = 0.f;
#pragma unroll
        for (int t = 0; t < 8; t++) s += wr[t];
        inv_s = 1.f / fmaxf(sqrtf(s), 1e-12f);
    }
    __syncthreads();
#pragma unroll
    for (int r = 0; r < 4; r++)
        out[n * 1024 + r * 256 + tid] = v[r] * inv_s;
}

// ---------------------------------------------------------------------------
extern "C" void kernel_launch(void* const* d_in, const int* in_sizes, int n_in,
                              void* d_out, int out_size) {
    const float* x         = (const float*)d_in[0];
    const float* Wpool     = (const float*)d_in[1];
    const float* bpool     = (const float*)d_in[2];
    const float* Wconv     = (const float*)d_in[3];
    const float* bconv     = (const float*)d_in[4];
    const float* centroids = (const float*)d_in[5];
    const float* Wproj     = (const float*)d_in[6];
    const float* bproj     = (const float*)d_in[7];
    float* out = (float*)d_out;

    cudaFuncSetAttribute(kA, cudaFuncAttributeMaxDynamicSharedMemorySize, 78592);

    kW<<<512, 256>>>(Wpool);
    kZ<<<1024, 256>>>();
    dim3 gA(13, 32);
    kA<<<gA, 256, 78592>>>(x, bpool, Wconv, bconv);
    dim3 gB(4, 32);
    kBfin<<<gB, 256>>>(centroids);
    dim3 gC(8, 16);
    kC<<<gC, 256>>>(Wproj);
    kD<<<32, 256>>>(bproj, out);
}

// round 10
// speedup vs baseline: 1.2272x; 1.2272x over previous
#include <cuda_runtime.h>
#include <cuda_fp16.h>
#include <cstdint>

// ---------------------------------------------------------------------------
// NetVLAD GB300 round 9: fp16 2-term split mma.sync pool GEMM
// w = wh + wl (fp16 planes), x rounded once to fp16: w*x ~= wh*xh + wl*xh
// N=32, C=1024, D=128, K=64, S=784 (13 tiles of 64), OUT=1024
// ---------------------------------------------------------------------------

__device__ __half g_wh[131072];           // Wpool hi [d][c]
__device__ __half g_wl[131072];           // Wpool lo [d][c]
__device__ float g_vladraw[32 * 8192];
__device__ float g_vlad  [32 * 8192];
__device__ float g_sasum [32 * 64];
__device__ float g_proj  [32 * 1024];

#define FMA2(acc, a, b) \
    asm("fma.rn.f32x2 %0, %1, %2, %0;" : "+l"(acc) : "l"(a), "l"(b))
#define DUP2(d, s) \
    asm("mov.b64 %0, {%1, %1};" : "=l"(d) : "f"(s))
#define UNPK(lo, hi, s) \
    asm("mov.b64 {%0, %1}, %2;" : "=f"(lo), "=f"(hi) : "l"(s))

__device__ __forceinline__ uint32_t smem_u32(const void* p) {
    uint32_t a;
    asm("{ .reg .u64 t; cvta.to.shared.u64 t, %1; cvt.u32.u64 %0, t; }"
        : "=r"(a) : "l"(p));
    return a;
}
__device__ __forceinline__ void ldsm(unsigned* r, uint32_t a) {
    asm volatile("ldmatrix.sync.aligned.m8n8.x4.shared.b16 {%0,%1,%2,%3}, [%4];"
        : "=r"(r[0]), "=r"(r[1]), "=r"(r[2]), "=r"(r[3]) : "r"(a));
}
__device__ __forceinline__ void ldsmt(unsigned* r, uint32_t a) {
    asm volatile("ldmatrix.sync.aligned.m8n8.x4.trans.shared.b16 {%0,%1,%2,%3}, [%4];"
        : "=r"(r[0]), "=r"(r[1]), "=r"(r[2]), "=r"(r[3]) : "r"(a));
}
__device__ __forceinline__ void mma_f16(float* c, const unsigned* a, const unsigned* b) {
    asm volatile(
        "mma.sync.aligned.m16n8k16.row.col.f32.f16.f16.f32 "
        "{%0,%1,%2,%3}, {%4,%5,%6,%7}, {%8,%9}, {%0,%1,%2,%3};"
        : "+f"(c[0]), "+f"(c[1]), "+f"(c[2]), "+f"(c[3])
        : "r"(a[0]), "r"(a[1]), "r"(a[2]), "r"(a[3]), "r"(b[0]), "r"(b[1]));
}

// ---------------------------------------------------------------------------
__global__ void kW(const float* __restrict__ Wpool) {
    int idx = blockIdx.x * 256 + threadIdx.x;
    if (idx >= 131072) return;
    float w = Wpool[idx];
    __half h = __float2half_rn(w);
    g_wh[idx] = h;
    g_wl[idx] = __float2half_rn(w - __half2float(h));
}

__global__ void kZ() {
    int idx = blockIdx.x * 256 + threadIdx.x;
    if (idx < 262144) g_vladraw[idx] = 0.f;
    if (idx < 2048)   g_sasum[idx] = 0.f;
    if (idx < 32768)  g_proj[idx] = 0.f;
}

// ---------------------------------------------------------------------------
// kA: fp16 2-term mma pool GEMM (128d x 64s) + bias + col L2 norm + logits
//     + softmax + fused vlad partial.  grid (13, 32), 256 thr, smem 78592 B
// phase1 bytes: WH@1024 [128][72 f16] 18432 | WL@19456 18432 | XH@37888
//   [64][72 f16] 9216  (ends 47104)
// phase2 floats: XF_A@256 [128][68] (acc -> WconvT -> saT)
//   XF_B@8960 [64 s][132 d] | EP3@17408 [64][34] | EP4@19584 [64]
// ---------------------------------------------------------------------------
__global__ void __launch_bounds__(256, 2) kA(const float* __restrict__ x,
                                             const float* __restrict__ bpool,
                                             const float* __restrict__ Wconv,
                                             const float* __restrict__ bconv) {
    extern __shared__ char smc[];
    float* smf = (float*)smc;
    const uint32_t sb = smem_u32(smc);

    const int tid = threadIdx.x, lane = tid & 31, wid = tid >> 5;
    const int n = blockIdx.y;
    const int s0 = blockIdx.x * 64;
    const bool fullv = (blockIdx.x < 12);

    const int WHo = 1024, WLo = 19456, XHo = 37888;
    const int XF_A = 256, XF_B = 8960, EP3 = 17408, EP4 = 19584;

    const float* xn = x + (size_t)n * 1024 * 784;
    const int xc = tid >> 2, xs = (tid & 3) * 16;     // X staging: c row, s sub
    const int wrow = tid >> 1, wcol = (tid & 1) * 32; // W staging

    const int wd = wid & 3, ws = wid >> 2;
    const int md0 = wd * 32, ns0 = ws * 32;
    const int mat = lane >> 3, rr = lane & 7;
    const uint32_t aH = sb + WHo + (uint32_t)(md0 + ((mat & 1) << 3) + rr) * 144
                        + ((uint32_t)(mat >> 1) << 4);
    const uint32_t aL = aH + 18432;
    const uint32_t bHb = sb + XHo + (uint32_t)(((mat & 1) << 3) + rr) * 144
                         + (uint32_t)(ns0 + ((mat >> 1) << 3)) * 2;

    float acc[2][4][4];
#pragma unroll
    for (int mt = 0; mt < 2; mt++)
#pragma unroll
        for (int nf = 0; nf < 4; nf++)
#pragma unroll
            for (int u = 0; u < 4; u++) acc[mt][nf][u] = 0.f;

    for (int q = 0; q < 16; q++) {
        if (q) __syncthreads();
        // ---- W chunk: 32 fp16 per plane per thread (pre-split) ----
        {
            const uint4* ph = (const uint4*)(g_wh + (size_t)wrow * 1024 + q * 64 + wcol);
            const uint4* pl = (const uint4*)(g_wl + (size_t)wrow * 1024 + q * 64 + wcol);
            uint4 h[4], l4[4];
#pragma unroll
            for (int u = 0; u < 4; u++) { h[u] = ph[u]; l4[u] = pl[u]; }
            char* dh = smc + WHo + wrow * 144 + wcol * 2;
            char* dl = smc + WLo + wrow * 144 + wcol * 2;
#pragma unroll
            for (int u = 0; u < 4; u++) {
                ((uint4*)dh)[u] = h[u];
                ((uint4*)dl)[u] = l4[u];
            }
        }
        // ---- X chunk: one c-row x 16 s, round once to fp16 ----
        {
            const float* p0 = xn + (size_t)(q * 64 + xc) * 784 + s0 + xs;
            float t[16];
            if (fullv) {
#pragma unroll
                for (int u = 0; u < 4; u++) {
                    float4 a = ((const float4*)p0)[u];
                    t[u * 4] = a.x; t[u * 4 + 1] = a.y;
                    t[u * 4 + 2] = a.z; t[u * 4 + 3] = a.w;
                }
            } else {
#pragma unroll
                for (int i = 0; i < 16; i++)
                    t[i] = ((s0 + xs + i) < 784) ? p0[i] : 0.f;
            }
            char* xh = smc + XHo + xc * 144 + xs * 2;
#pragma unroll
            for (int i = 0; i < 8; i++) {
                __half2 hp = __floats2half2_rn(t[2 * i], t[2 * i + 1]);
                *(uint32_t*)(xh + i * 4) = *(uint32_t*)&hp;
            }
        }
        __syncthreads();
        // ---- mma: k = 64 in 4 k-steps of 16, 2 terms each ----
#pragma unroll
        for (int ks = 0; ks < 4; ks++) {
            unsigned ah[2][4], al[2][4];
            ldsm(ah[0], aH + ks * 32);
            ldsm(ah[1], aH + ks * 32 + 2304);
            ldsm(al[0], aL + ks * 32);
            ldsm(al[1], aL + ks * 32 + 2304);
            unsigned bh[2][4];
#pragma unroll
            for (int nt = 0; nt < 2; nt++)
                ldsmt(bh[nt], bHb + ks * 2304 + nt * 32);
#pragma unroll
            for (int mt = 0; mt < 2; mt++)
#pragma unroll
                for (int nf = 0; nf < 4; nf++) {
                    const unsigned* bhf = &bh[nf >> 1][(nf & 1) * 2];
                    mma_f16(acc[mt][nf], ah[mt], bhf);
                    mma_f16(acc[mt][nf], al[mt], bhf);
                }
        }
    }
    __syncthreads();

    // ---- acc -> XF_A[d][s] (+bias) ----
    {
        const int r0w = lane >> 2, cq = (lane & 3) * 2;
#pragma unroll
        for (int mt = 0; mt < 2; mt++) {
            int d = md0 + mt * 16 + r0w;
            float b0 = __ldg(&bpool[d]);
            float b8 = __ldg(&bpool[d + 8]);
#pragma unroll
            for (int nf = 0; nf < 4; nf++) {
                int s = ns0 + nf * 8 + cq;
                smf[XF_A + d * 68 + s]           = acc[mt][nf][0] + b0;
                smf[XF_A + d * 68 + s + 1]       = acc[mt][nf][1] + b0;
                smf[XF_A + (d + 8) * 68 + s]     = acc[mt][nf][2] + b8;
                smf[XF_A + (d + 8) * 68 + s + 1] = acc[mt][nf][3] + b8;
            }
        }
    }
    __syncthreads();

    // ---- column L2 norm over d ----
    if (tid < 64) {
        float s = 0.f;
#pragma unroll 8
        for (int d = 0; d < 128; d++) {
            float v = smf[XF_A + d * 68 + tid];
            s += v * v;
        }
        smf[EP4 + tid] = ((s0 + tid) < 784) ? 1.f / fmaxf(sqrtf(s), 1e-12f) : 0.f;
    }
    __syncthreads();

    // ---- build normalized XF_B[s][d] ----
    {
        const int row = tid & 127, hs = tid >> 7;
#pragma unroll
        for (int g = 0; g < 8; g++) {
            int s4 = hs * 32 + g * 4;
            float4 v = *(const float4*)&smf[XF_A + row * 68 + s4];
            float4 m = *(const float4*)&smf[EP4 + s4];
            smf[XF_B + (s4 + 0) * 132 + row] = v.x * m.x;
            smf[XF_B + (s4 + 1) * 132 + row] = v.y * m.y;
            smf[XF_B + (s4 + 2) * 132 + row] = v.z * m.z;
            smf[XF_B + (s4 + 3) * 132 + row] = v.w * m.w;
        }
    }
    __syncthreads();

    // ---- stage WconvT[d][k] into XF_A region ----
    {
        int kr = tid & 63, dq = tid >> 6;
#pragma unroll
        for (int u = 0; u < 8; u++) {
            float4 w = *(const float4*)&Wconv[kr * 128 + dq * 32 + u * 4];
            smf[XF_A + (dq * 32 + u * 4 + 0) * 68 + kr] = w.x;
            smf[XF_A + (dq * 32 + u * 4 + 1) * 68 + kr] = w.y;
            smf[XF_A + (dq * 32 + u * 4 + 2) * 68 + kr] = w.z;
            smf[XF_A + (dq * 32 + u * 4 + 3) * 68 + kr] = w.w;
        }
    }
    __syncthreads();

    // ---- logits: kg -> 8 k, sc -> s pair ----
    const int kg = tid & 7;
    const int sc = tid >> 3;
    unsigned long long a2[4][2];
#pragma unroll
    for (int p = 0; p < 4; p++) { a2[p][0] = 0ull; a2[p][1] = 0ull; }
    for (int d = 0; d < 128; d++) {
        ulonglong2 w0 = *(const ulonglong2*)&smf[XF_A + d * 68 + kg * 8];
        ulonglong2 w1 = *(const ulonglong2*)&smf[XF_A + d * 68 + kg * 8 + 4];
        float x0 = smf[XF_B + (2 * sc) * 132 + d];
        float x1 = smf[XF_B + (2 * sc + 1) * 132 + d];
        unsigned long long xd0, xd1;
        DUP2(xd0, x0); DUP2(xd1, x1);
        FMA2(a2[0][0], w0.x, xd0); FMA2(a2[0][1], w0.x, xd1);
        FMA2(a2[1][0], w0.y, xd0); FMA2(a2[1][1], w0.y, xd1);
        FMA2(a2[2][0], w1.x, xd0); FMA2(a2[2][1], w1.x, xd1);
        FMA2(a2[3][0], w1.y, xd0); FMA2(a2[3][1], w1.y, xd1);
    }
    float l[8][2];
#pragma unroll
    for (int p = 0; p < 4; p++) {
        UNPK(l[2 * p][0], l[2 * p + 1][0], a2[p][0]);
        UNPK(l[2 * p][1], l[2 * p + 1][1], a2[p][1]);
    }
#pragma unroll
    for (int i = 0; i < 8; i++) {
        float b = bconv[kg * 8 + i];
        l[i][0] += b; l[i][1] += b;
    }

    // ---- softmax over K per column ----
#pragma unroll
    for (int j = 0; j < 2; j++) {
        float m = l[0][j];
#pragma unroll
        for (int i = 1; i < 8; i++) m = fmaxf(m, l[i][j]);
        smf[EP3 + (2 * sc + j) * 17 + kg] = m;
    }
    __syncthreads();
    if (tid < 64) {
        float m = smf[EP3 + tid * 17];
#pragma unroll
        for (int t = 1; t < 8; t++) m = fmaxf(m, smf[EP3 + tid * 17 + t]);
        smf[EP4 + tid] = m;
    }
    __syncthreads();
    float e[8][2];
#pragma unroll
    for (int j = 0; j < 2; j++) {
        float M = smf[EP4 + 2 * sc + j];
        float ssum = 0.f;
#pragma unroll
        for (int i = 0; i < 8; i++) { e[i][j] = __expf(l[i][j] - M); ssum += e[i][j]; }
        smf[EP3 + (2 * sc + j) * 17 + kg] = ssum;
    }
    __syncthreads();
    if (tid < 64) {
        float t = 0.f;
#pragma unroll
        for (int qq = 0; qq < 8; qq++) t += smf[EP3 + tid * 17 + qq];
        smf[EP4 + tid] = 1.f / t;
    }
    __syncthreads();

    // ---- saT[s][k] into XF_A + sasum partials ----
    float ps[8];
#pragma unroll
    for (int i = 0; i < 8; i++) ps[i] = 0.f;
#pragma unroll
    for (int j = 0; j < 2; j++) {
        int sl = 2 * sc + j;
        float r = ((s0 + sl) < 784) ? smf[EP4 + sl] : 0.f;
#pragma unroll
        for (int i = 0; i < 8; i++) {
            float val = e[i][j] * r;
            smf[XF_A + sl * 68 + kg * 8 + i] = val;
            ps[i] += val;
        }
    }
    __syncthreads();
#pragma unroll
    for (int i = 0; i < 8; i++)
        smf[EP3 + (kg * 8 + i) * 34 + sc] = ps[i];
    __syncthreads();
    if (tid < 64) {
        float s = 0.f;
#pragma unroll
        for (int c = 0; c < 32; c++) s += smf[EP3 + tid * 34 + c];
        atomicAdd(&g_sasum[n * 64 + tid], s);
    }

    // ---- vlad partial: saT @ XF_B -> g_vladraw ----
    const int tk = tid >> 4;
    const int dg = tid & 15;
    unsigned long long vacc[4][4];
#pragma unroll
    for (int qk = 0; qk < 4; qk++)
#pragma unroll
        for (int p = 0; p < 4; p++) vacc[qk][p] = 0ull;
    for (int s = 0; s < 64; s++) {
        float4 sv = *(const float4*)&smf[XF_A + s * 68 + tk * 4];
        ulonglong2 xa = *(const ulonglong2*)&smf[XF_B + s * 132 + dg * 8];
        ulonglong2 xb = *(const ulonglong2*)&smf[XF_B + s * 132 + dg * 8 + 4];
        unsigned long long d0, d1, d2, d3;
        DUP2(d0, sv.x); DUP2(d1, sv.y); DUP2(d2, sv.z); DUP2(d3, sv.w);
        FMA2(vacc[0][0], d0, xa.x); FMA2(vacc[0][1], d0, xa.y);
        FMA2(vacc[0][2], d0, xb.x); FMA2(vacc[0][3], d0, xb.y);
        FMA2(vacc[1][0], d1, xa.x); FMA2(vacc[1][1], d1, xa.y);
        FMA2(vacc[1][2], d1, xb.x); FMA2(vacc[1][3], d1, xb.y);
        FMA2(vacc[2][0], d2, xa.x); FMA2(vacc[2][1], d2, xa.y);
        FMA2(vacc[2][2], d2, xb.x); FMA2(vacc[2][3], d2, xb.y);
        FMA2(vacc[3][0], d3, xa.x); FMA2(vacc[3][1], d3, xa.y);
        FMA2(vacc[3][2], d3, xb.x); FMA2(vacc[3][3], d3, xb.y);
    }
    float* vr = g_vladraw + (size_t)n * 8192;
#pragma unroll
    for (int qk = 0; qk < 4; qk++)
#pragma unroll
        for (int p = 0; p < 4; p++) {
            float lo, hi;
            UNPK(lo, hi, vacc[qk][p]);
            int base = (tk * 4 + qk) * 128 + dg * 8 + p * 2;
            atomicAdd(&vr[base], lo);
            atomicAdd(&vr[base + 1], hi);
        }
}

// ---------------------------------------------------------------------------
// kBfin: vlad = vladraw - centroids*sasum, intra-norm over K
// grid (4 d-tiles, 32 n), 256 thr = 32 d x 8 k-groups
// ---------------------------------------------------------------------------
__global__ void __launch_bounds__(256) kBfin(const float* __restrict__ centroids) {
    __shared__ float ssm[64];
    __shared__ float red[8][33];
    const int dt = blockIdx.x, n = blockIdx.y, tid = threadIdx.x;
    const int dl = tid & 31, kg = tid >> 5;
    const int d = dt * 32 + dl;
    if (tid < 64) ssm[tid] = g_sasum[n * 64 + tid];
    __syncthreads();
    const float* vr = g_vladraw + (size_t)n * 8192;
    float v[8], sq = 0.f;
#pragma unroll
    for (int j = 0; j < 8; j++) {
        int k = kg * 8 + j;
        float val = vr[k * 128 + d] - centroids[k * 128 + d] * ssm[k];
        v[j] = val;
        sq += val * val;
    }
    red[kg][dl] = sq;
    __syncthreads();
    float tot = 0.f;
#pragma unroll
    for (int t = 0; t < 8; t++) tot += red[t][dl];
    float inv = 1.f / fmaxf(sqrtf(tot), 1e-12f);
    float* vo = g_vlad + (size_t)n * 8192;
#pragma unroll
    for (int j = 0; j < 8; j++)
        vo[(kg * 8 + j) * 128 + d] = v[j] * inv;
}

// ---------------------------------------------------------------------------
// kC: proj += vlad @ Wproj^T.  grid (8 o-tiles of 128, 16 j-splits of 512)
// ---------------------------------------------------------------------------
__global__ void __launch_bounds__(256) kC(const float* __restrict__ Wproj) {
    __shared__ float wT[32 * 132];   // [j][o]
    __shared__ float vT[32 * 36];    // [j][n]
    const int tid = threadIdx.x;
    const int ob = blockIdx.x * 128;
    const int jb = blockIdx.y * 512;
    const int og = tid >> 4;
    const int ng = tid & 15;

    unsigned long long acc[8];
#pragma unroll
    for (int i = 0; i < 8; i++) acc[i] = 0ull;

    const int wo = tid >> 1, wj = (tid & 1) * 16;
    const int vn = tid >> 3, vj = (tid & 7) * 4;

    for (int jt = 0; jt < 512; jt += 32) {
        __syncthreads();
        {
            const float* wr = &Wproj[(size_t)(ob + wo) * 8192 + jb + jt + wj];
#pragma unroll
            for (int u = 0; u < 4; u++) {
                float4 w = *(const float4*)&wr[u * 4];
                wT[(wj + u * 4 + 0) * 132 + wo] = w.x;
                wT[(wj + u * 4 + 1) * 132 + wo] = w.y;
                wT[(wj + u * 4 + 2) * 132 + wo] = w.z;
                wT[(wj + u * 4 + 3) * 132 + wo] = w.w;
            }
            float4 v = *(const float4*)&g_vlad[(size_t)vn * 8192 + jb + jt + vj];
            vT[(vj + 0) * 36 + vn] = v.x;
            vT[(vj + 1) * 36 + vn] = v.y;
            vT[(vj + 2) * 36 + vn] = v.z;
            vT[(vj + 3) * 36 + vn] = v.w;
        }
        __syncthreads();
#pragma unroll
        for (int j = 0; j < 32; j++) {
            float4 w0 = *(const float4*)&wT[j * 132 + og * 8];
            float4 w1 = *(const float4*)&wT[j * 132 + og * 8 + 4];
            unsigned long long vp = *(const unsigned long long*)&vT[j * 36 + ng * 2];
            unsigned long long wdr[8];
            DUP2(wdr[0], w0.x); DUP2(wdr[1], w0.y); DUP2(wdr[2], w0.z); DUP2(wdr[3], w0.w);
            DUP2(wdr[4], w1.x); DUP2(wdr[5], w1.y); DUP2(wdr[6], w1.z); DUP2(wdr[7], w1.w);
#pragma unroll
            for (int i = 0; i < 8; i++) FMA2(acc[i], wdr[i], vp);
        }
    }
#pragma unroll
    for (int i = 0; i < 8; i++) {
        float lo, hi;
        UNPK(lo, hi, acc[i]);
        int o = ob + og * 8 + i;
        atomicAdd(&g_proj[(ng * 2 + 0) * 1024 + o], lo);
        atomicAdd(&g_proj[(ng * 2 + 1) * 1024 + o], hi);
    }
}

// ---------------------------------------------------------------------------
__global__ void __launch_bounds__(256) kD(const float* __restrict__ bproj,
                                          float* __restrict__ out) {
    __shared__ float wr[8];
    __shared__ float inv_s;
    const int n = blockIdx.x, tid = threadIdx.x;
    float v[4]; float ps = 0.f;
#pragma unroll
    for (int r = 0; r < 4; r++) {
        int o = r * 256 + tid;
        v[r] = g_proj[n * 1024 + o] + bproj[o];
        ps += v[r] * v[r];
    }
#pragma unroll
    for (int off = 16; off; off >>= 1)
        ps += __shfl_xor_sync(0xffffffffu, ps, off);
    if ((tid & 31) == 0) wr[tid >> 5] = ps;
    __syncthreads();
    if (tid == 0) {
        float s = 0.f;
#pragma unroll
        for (int t = 0; t < 8; t++) s += wr[t];
        inv_s = 1.f / fmaxf(sqrtf(s), 1e-12f);
    }
    __syncthreads();
#pragma unroll
    for (int r = 0; r < 4; r++)
        out[n * 1024 + r * 256 + tid] = v[r] * inv_s;
}

// ---------------------------------------------------------------------------
extern "C" void kernel_launch(void* const* d_in, const int* in_sizes, int n_in,
                              void* d_out, int out_size) {
    const float* x         = (const float*)d_in[0];
    const float* Wpool     = (const float*)d_in[1];
    const float* bpool     = (const float*)d_in[2];
    const float* Wconv     = (const float*)d_in[3];
    const float* bconv     = (const float*)d_in[4];
    const float* centroids = (const float*)d_in[5];
    const float* Wproj     = (const float*)d_in[6];
    const float* bproj     = (const float*)d_in[7];
    float* out = (float*)d_out;

    cudaFuncSetAttribute(kA, cudaFuncAttributeMaxDynamicSharedMemorySize, 78592);

    kW<<<512, 256>>>(Wpool);
    kZ<<<1024, 256>>>();
    dim3 gA(13, 32);
    kA<<<gA, 256, 78592>>>(x, bpool, Wconv, bconv);
    dim3 gB(4, 32);
    kBfin<<<gB, 256>>>(centroids);
    dim3 gC(8, 16);
    kC<<<gC, 256>>>(Wproj);
    kD<<<32, 256>>>(bproj, out);
}

// round 11
// speedup vs baseline: 1.4744x; 1.2015x over previous
#include <cuda_runtime.h>
#include <cuda_fp16.h>
#include <cstdint>

// ---------------------------------------------------------------------------
// NetVLAD GB300 round 10: fp16 2-term mma + cp.async W pipeline + X reg prefetch
// N=32, C=1024, D=128, K=64, S=784 (13 tiles of 64), OUT=1024
// ---------------------------------------------------------------------------

__device__ __align__(16) unsigned char g_wpk[589824];  // 16 chunks x 36864B smem image
__device__ float g_vladraw[32 * 8192];
__device__ float g_vlad  [32 * 8192];
__device__ float g_sasum [32 * 64];
__device__ float g_proj  [32 * 1024];

#define FMA2(acc, a, b) \
    asm("fma.rn.f32x2 %0, %1, %2, %0;" : "+l"(acc) : "l"(a), "l"(b))
#define DUP2(d, s) \
    asm("mov.b64 %0, {%1, %1};" : "=l"(d) : "f"(s))
#define UNPK(lo, hi, s) \
    asm("mov.b64 {%0, %1}, %2;" : "=f"(lo), "=f"(hi) : "l"(s))

__device__ __forceinline__ uint32_t smem_u32(const void* p) {
    uint32_t a;
    asm("{ .reg .u64 t; cvta.to.shared.u64 t, %1; cvt.u32.u64 %0, t; }"
        : "=r"(a) : "l"(p));
    return a;
}
__device__ __forceinline__ void cpasync16(uint32_t smem, const void* gmem) {
    asm volatile("cp.async.cg.shared.global [%0], [%1], 16;"
        :: "r"(smem), "l"(gmem) : "memory");
}
#define CP_COMMIT() asm volatile("cp.async.commit_group;" ::: "memory")
#define CP_WAIT1()  asm volatile("cp.async.wait_group 1;" ::: "memory")

__device__ __forceinline__ void ldsm(unsigned* r, uint32_t a) {
    asm volatile("ldmatrix.sync.aligned.m8n8.x4.shared.b16 {%0,%1,%2,%3}, [%4];"
        : "=r"(r[0]), "=r"(r[1]), "=r"(r[2]), "=r"(r[3]) : "r"(a));
}
__device__ __forceinline__ void ldsmt(unsigned* r, uint32_t a) {
    asm volatile("ldmatrix.sync.aligned.m8n8.x4.trans.shared.b16 {%0,%1,%2,%3}, [%4];"
        : "=r"(r[0]), "=r"(r[1]), "=r"(r[2]), "=r"(r[3]) : "r"(a));
}
__device__ __forceinline__ void mma_f16(float* c, const unsigned* a, const unsigned* b) {
    asm volatile(
        "mma.sync.aligned.m16n8k16.row.col.f32.f16.f16.f32 "
        "{%0,%1,%2,%3}, {%4,%5,%6,%7}, {%8,%9}, {%0,%1,%2,%3};"
        : "+f"(c[0]), "+f"(c[1]), "+f"(c[2]), "+f"(c[3])
        : "r"(a[0]), "r"(a[1]), "r"(a[2]), "r"(a[3]), "r"(b[0]), "r"(b[1]));
}

// ---------------------------------------------------------------------------
// kW: split Wpool into fp16 hi/lo and pack in per-chunk smem image layout:
// chunk q (c in [64q,64q+64)): WH [128 d][72 f16] (144B rows) | WL same @+18432
// ---------------------------------------------------------------------------
__global__ void kW(const float* __restrict__ Wpool) {
    int idx = blockIdx.x * 256 + threadIdx.x;
    if (idx >= 131072) return;
    int d = idx >> 10, c = idx & 1023;
    float w = Wpool[idx];
    __half h = __float2half_rn(w);
    __half l = __float2half_rn(w - __half2float(h));
    int q = c >> 6, cl = c & 63;
    *(__half*)(g_wpk + q * 36864 + d * 144 + cl * 2) = h;
    *(__half*)(g_wpk + q * 36864 + 18432 + d * 144 + cl * 2) = l;
}

__global__ void kZ() {
    int idx = blockIdx.x * 256 + threadIdx.x;
    if (idx < 262144) g_vladraw[idx] = 0.f;
    if (idx < 2048)   g_sasum[idx] = 0.f;
    if (idx < 32768)  g_proj[idx] = 0.f;
}

// ---------------------------------------------------------------------------
// kA: fp16 2-term mma pool GEMM (128d x 64s), cp.async W double-buffer,
//     X register prefetch.  grid (13, 32), 256 thr, dyn smem 93184 B
// phase1 bytes: BUF(b) @ 1024 + b*46080:  WH 18432 | WL 18432 | X 9216
// phase2 floats: XF_A@256 [128][68] | XF_B@8960 [64][132] | EP3@17408 [64][34]
//                | EP4@19584 [64]
// ---------------------------------------------------------------------------
__global__ void __launch_bounds__(256, 2) kA(const float* __restrict__ x,
                                             const float* __restrict__ bpool,
                                             const float* __restrict__ Wconv,
                                             const float* __restrict__ bconv) {
    extern __shared__ char smc[];
    float* smf = (float*)smc;
    const uint32_t sb = smem_u32(smc);

    const int tid = threadIdx.x, lane = tid & 31, wid = tid >> 5;
    const int n = blockIdx.y;
    const int s0 = blockIdx.x * 64;
    const bool fullv = (blockIdx.x < 12);

    const int XF_A = 256, XF_B = 8960, EP3 = 17408, EP4 = 19584;

    const float* xn = x + (size_t)n * 1024 * 784;
    const int xc = tid >> 2, xs = (tid & 3) * 16;   // X: c row, s sub-base

    const int wd = wid & 3, ws = wid >> 2;
    const int md0 = wd * 32, ns0 = ws * 32;
    const int mat = lane >> 3, rr = lane & 7;
    // fragment bases for buffer 0 (add 46080 for buffer 1)
    const uint32_t aH0 = sb + 1024 + (uint32_t)(md0 + ((mat & 1) << 3) + rr) * 144
                         + ((uint32_t)(mat >> 1) << 4);
    const uint32_t bH0 = sb + 1024 + 36864 + (uint32_t)(((mat & 1) << 3) + rr) * 144
                         + (uint32_t)(ns0 + ((mat >> 1) << 3)) * 2;

    float acc[2][4][4];
#pragma unroll
    for (int mt = 0; mt < 2; mt++)
#pragma unroll
        for (int nf = 0; nf < 4; nf++)
#pragma unroll
            for (int u = 0; u < 4; u++) acc[mt][nf][u] = 0.f;

    float xr[16];

#define LOADX(q) do { \
    const float* p0 = xn + (size_t)((q) * 64 + xc) * 784 + s0 + xs; \
    if (fullv) { \
        _Pragma("unroll") \
        for (int u = 0; u < 4; u++) { \
            float4 a4 = ((const float4*)p0)[u]; \
            xr[u * 4] = a4.x; xr[u * 4 + 1] = a4.y; \
            xr[u * 4 + 2] = a4.z; xr[u * 4 + 3] = a4.w; \
        } \
    } else { \
        _Pragma("unroll") \
        for (int i = 0; i < 16; i++) \
            xr[i] = ((s0 + xs + i) < 784) ? p0[i] : 0.f; \
    } } while (0)

#define STOREX(b) do { \
    char* xh = smc + 1024 + (b) * 46080 + 36864 + xc * 144 + xs * 2; \
    _Pragma("unroll") \
    for (int i = 0; i < 8; i++) { \
        __half2 hp = __floats2half2_rn(xr[2 * i], xr[2 * i + 1]); \
        *(uint32_t*)(xh + i * 4) = *(uint32_t*)&hp; \
    } } while (0)

#define COPYW(q, b) do { \
    const unsigned char* src = g_wpk + (q) * 36864; \
    uint32_t dst = sb + 1024 + (b) * 46080; \
    _Pragma("unroll") \
    for (int i = 0; i < 9; i++) { \
        int seg = tid + i * 256; \
        cpasync16(dst + seg * 16, src + seg * 16); \
    } } while (0)

    // prologue
    LOADX(0);
    COPYW(0, 0); CP_COMMIT();
    COPYW(1, 1); CP_COMMIT();

    for (int q = 0; q < 16; q++) {
        const int b = q & 1;
        STOREX(b);
        if (q + 1 < 16) LOADX(q + 1);
        CP_WAIT1();
        __syncthreads();

        const uint32_t aH = aH0 + b * 46080;
        const uint32_t aL = aH + 18432;
        const uint32_t bH = bH0 + b * 46080;
#pragma unroll
        for (int ks = 0; ks < 4; ks++) {
            unsigned ah[2][4], al[2][4];
            ldsm(ah[0], aH + ks * 32);
            ldsm(ah[1], aH + ks * 32 + 2304);
            ldsm(al[0], aL + ks * 32);
            ldsm(al[1], aL + ks * 32 + 2304);
            unsigned bh[2][4];
#pragma unroll
            for (int nt = 0; nt < 2; nt++)
                ldsmt(bh[nt], bH + ks * 2304 + nt * 32);
#pragma unroll
            for (int mt = 0; mt < 2; mt++)
#pragma unroll
                for (int nf = 0; nf < 4; nf++) {
                    const unsigned* bhf = &bh[nf >> 1][(nf & 1) * 2];
                    mma_f16(acc[mt][nf], ah[mt], bhf);
                    mma_f16(acc[mt][nf], al[mt], bhf);
                }
        }
        __syncthreads();
        if (q + 2 < 16) COPYW(q + 2, b);
        CP_COMMIT();
    }
#undef LOADX
#undef STOREX
#undef COPYW

    // ---- acc -> XF_A[d][s] (+bias) ----
    {
        const int r0w = lane >> 2, cq = (lane & 3) * 2;
#pragma unroll
        for (int mt = 0; mt < 2; mt++) {
            int d = md0 + mt * 16 + r0w;
            float b0 = __ldg(&bpool[d]);
            float b8 = __ldg(&bpool[d + 8]);
#pragma unroll
            for (int nf = 0; nf < 4; nf++) {
                int s = ns0 + nf * 8 + cq;
                smf[XF_A + d * 68 + s]           = acc[mt][nf][0] + b0;
                smf[XF_A + d * 68 + s + 1]       = acc[mt][nf][1] + b0;
                smf[XF_A + (d + 8) * 68 + s]     = acc[mt][nf][2] + b8;
                smf[XF_A + (d + 8) * 68 + s + 1] = acc[mt][nf][3] + b8;
            }
        }
    }
    __syncthreads();

    // ---- column L2 norm over d ----
    if (tid < 64) {
        float s = 0.f;
#pragma unroll 8
        for (int d = 0; d < 128; d++) {
            float v = smf[XF_A + d * 68 + tid];
            s += v * v;
        }
        smf[EP4 + tid] = ((s0 + tid) < 784) ? 1.f / fmaxf(sqrtf(s), 1e-12f) : 0.f;
    }
    __syncthreads();

    // ---- build normalized XF_B[s][d] ----
    {
        const int row = tid & 127, hs = tid >> 7;
#pragma unroll
        for (int g = 0; g < 8; g++) {
            int s4 = hs * 32 + g * 4;
            float4 v = *(const float4*)&smf[XF_A + row * 68 + s4];
            float4 m = *(const float4*)&smf[EP4 + s4];
            smf[XF_B + (s4 + 0) * 132 + row] = v.x * m.x;
            smf[XF_B + (s4 + 1) * 132 + row] = v.y * m.y;
            smf[XF_B + (s4 + 2) * 132 + row] = v.z * m.z;
            smf[XF_B + (s4 + 3) * 132 + row] = v.w * m.w;
        }
    }
    __syncthreads();

    // ---- stage WconvT[d][k] into XF_A region ----
    {
        int kr = tid & 63, dq = tid >> 6;
#pragma unroll
        for (int u = 0; u < 8; u++) {
            float4 w = *(const float4*)&Wconv[kr * 128 + dq * 32 + u * 4];
            smf[XF_A + (dq * 32 + u * 4 + 0) * 68 + kr] = w.x;
            smf[XF_A + (dq * 32 + u * 4 + 1) * 68 + kr] = w.y;
            smf[XF_A + (dq * 32 + u * 4 + 2) * 68 + kr] = w.z;
            smf[XF_A + (dq * 32 + u * 4 + 3) * 68 + kr] = w.w;
        }
    }
    __syncthreads();

    // ---- logits: kg -> 8 k, sc -> s pair ----
    const int kg = tid & 7;
    const int sc = tid >> 3;
    unsigned long long a2[4][2];
#pragma unroll
    for (int p = 0; p < 4; p++) { a2[p][0] = 0ull; a2[p][1] = 0ull; }
    for (int d = 0; d < 128; d++) {
        ulonglong2 w0 = *(const ulonglong2*)&smf[XF_A + d * 68 + kg * 8];
        ulonglong2 w1 = *(const ulonglong2*)&smf[XF_A + d * 68 + kg * 8 + 4];
        float x0 = smf[XF_B + (2 * sc) * 132 + d];
        float x1 = smf[XF_B + (2 * sc + 1) * 132 + d];
        unsigned long long xd0, xd1;
        DUP2(xd0, x0); DUP2(xd1, x1);
        FMA2(a2[0][0], w0.x, xd0); FMA2(a2[0][1], w0.x, xd1);
        FMA2(a2[1][0], w0.y, xd0); FMA2(a2[1][1], w0.y, xd1);
        FMA2(a2[2][0], w1.x, xd0); FMA2(a2[2][1], w1.x, xd1);
        FMA2(a2[3][0], w1.y, xd0); FMA2(a2[3][1], w1.y, xd1);
    }
    float l[8][2];
#pragma unroll
    for (int p = 0; p < 4; p++) {
        UNPK(l[2 * p][0], l[2 * p + 1][0], a2[p][0]);
        UNPK(l[2 * p][1], l[2 * p + 1][1], a2[p][1]);
    }
#pragma unroll
    for (int i = 0; i < 8; i++) {
        float b = bconv[kg * 8 + i];
        l[i][0] += b; l[i][1] += b;
    }

    // ---- softmax over K per column ----
#pragma unroll
    for (int j = 0; j < 2; j++) {
        float m = l[0][j];
#pragma unroll
        for (int i = 1; i < 8; i++) m = fmaxf(m, l[i][j]);
        smf[EP3 + (2 * sc + j) * 17 + kg] = m;
    }
    __syncthreads();
    if (tid < 64) {
        float m = smf[EP3 + tid * 17];
#pragma unroll
        for (int t = 1; t < 8; t++) m = fmaxf(m, smf[EP3 + tid * 17 + t]);
        smf[EP4 + tid] = m;
    }
    __syncthreads();
    float e[8][2];
#pragma unroll
    for (int j = 0; j < 2; j++) {
        float M = smf[EP4 + 2 * sc + j];
        float ssum = 0.f;
#pragma unroll
        for (int i = 0; i < 8; i++) { e[i][j] = __expf(l[i][j] - M); ssum += e[i][j]; }
        smf[EP3 + (2 * sc + j) * 17 + kg] = ssum;
    }
    __syncthreads();
    if (tid < 64) {
        float t = 0.f;
#pragma unroll
        for (int qq = 0; qq < 8; qq++) t += smf[EP3 + tid * 17 + qq];
        smf[EP4 + tid] = 1.f / t;
    }
    __syncthreads();

    // ---- saT[s][k] into XF_A + sasum partials ----
    float ps[8];
#pragma unroll
    for (int i = 0; i < 8; i++) ps[i] = 0.f;
#pragma unroll
    for (int j = 0; j < 2; j++) {
        int sl = 2 * sc + j;
        float r = ((s0 + sl) < 784) ? smf[EP4 + sl] : 0.f;
#pragma unroll
        for (int i = 0; i < 8; i++) {
            float val = e[i][j] * r;
            smf[XF_A + sl * 68 + kg * 8 + i] = val;
            ps[i] += val;
        }
    }
    __syncthreads();
#pragma unroll
    for (int i = 0; i < 8; i++)
        smf[EP3 + (kg * 8 + i) * 34 + sc] = ps[i];
    __syncthreads();
    if (tid < 64) {
        float s = 0.f;
#pragma unroll
        for (int c = 0; c < 32; c++) s += smf[EP3 + tid * 34 + c];
        atomicAdd(&g_sasum[n * 64 + tid], s);
    }

    // ---- vlad partial: saT @ XF_B -> g_vladraw ----
    const int tk = tid >> 4;
    const int dg = tid & 15;
    unsigned long long vacc[4][4];
#pragma unroll
    for (int qk = 0; qk < 4; qk++)
#pragma unroll
        for (int p = 0; p < 4; p++) vacc[qk][p] = 0ull;
    for (int s = 0; s < 64; s++) {
        float4 sv = *(const float4*)&smf[XF_A + s * 68 + tk * 4];
        ulonglong2 xa = *(const ulonglong2*)&smf[XF_B + s * 132 + dg * 8];
        ulonglong2 xb = *(const ulonglong2*)&smf[XF_B + s * 132 + dg * 8 + 4];
        unsigned long long d0, d1, d2, d3;
        DUP2(d0, sv.x); DUP2(d1, sv.y); DUP2(d2, sv.z); DUP2(d3, sv.w);
        FMA2(vacc[0][0], d0, xa.x); FMA2(vacc[0][1], d0, xa.y);
        FMA2(vacc[0][2], d0, xb.x); FMA2(vacc[0][3], d0, xb.y);
        FMA2(vacc[1][0], d1, xa.x); FMA2(vacc[1][1], d1, xa.y);
        FMA2(vacc[1][2], d1, xb.x); FMA2(vacc[1][3], d1, xb.y);
        FMA2(vacc[2][0], d2, xa.x); FMA2(vacc[2][1], d2, xa.y);
        FMA2(vacc[2][2], d2, xb.x); FMA2(vacc[2][3], d2, xb.y);
        FMA2(vacc[3][0], d3, xa.x); FMA2(vacc[3][1], d3, xa.y);
        FMA2(vacc[3][2], d3, xb.x); FMA2(vacc[3][3], d3, xb.y);
    }
    float* vr = g_vladraw + (size_t)n * 8192;
#pragma unroll
    for (int qk = 0; qk < 4; qk++)
#pragma unroll
        for (int p = 0; p < 4; p++) {
            float lo, hi;
            UNPK(lo, hi, vacc[qk][p]);
            int base = (tk * 4 + qk) * 128 + dg * 8 + p * 2;
            atomicAdd(&vr[base], lo);
            atomicAdd(&vr[base + 1], hi);
        }
}

// ---------------------------------------------------------------------------
// kBfin: vlad = vladraw - centroids*sasum, intra-norm over K
// ---------------------------------------------------------------------------
__global__ void __launch_bounds__(256) kBfin(const float* __restrict__ centroids) {
    __shared__ float ssm[64];
    __shared__ float red[8][33];
    const int dt = blockIdx.x, n = blockIdx.y, tid = threadIdx.x;
    const int dl = tid & 31, kg = tid >> 5;
    const int d = dt * 32 + dl;
    if (tid < 64) ssm[tid] = g_sasum[n * 64 + tid];
    __syncthreads();
    const float* vr = g_vladraw + (size_t)n * 8192;
    float v[8], sq = 0.f;
#pragma unroll
    for (int j = 0; j < 8; j++) {
        int k = kg * 8 + j;
        float val = vr[k * 128 + d] - centroids[k * 128 + d] * ssm[k];
        v[j] = val;
        sq += val * val;
    }
    red[kg][dl] = sq;
    __syncthreads();
    float tot = 0.f;
#pragma unroll
    for (int t = 0; t < 8; t++) tot += red[t][dl];
    float inv = 1.f / fmaxf(sqrtf(tot), 1e-12f);
    float* vo = g_vlad + (size_t)n * 8192;
#pragma unroll
    for (int j = 0; j < 8; j++)
        vo[(kg * 8 + j) * 128 + d] = v[j] * inv;
}

// ---------------------------------------------------------------------------
// kC: proj += vlad @ Wproj^T.  grid (8 o-tiles of 128, 16 j-splits of 512)
// ---------------------------------------------------------------------------
__global__ void __launch_bounds__(256) kC(const float* __restrict__ Wproj) {
    __shared__ float wT[32 * 132];
    __shared__ float vT[32 * 36];
    const int tid = threadIdx.x;
    const int ob = blockIdx.x * 128;
    const int jb = blockIdx.y * 512;
    const int og = tid >> 4;
    const int ng = tid & 15;

    unsigned long long acc[8];
#pragma unroll
    for (int i = 0; i < 8; i++) acc[i] = 0ull;

    const int wo = tid >> 1, wj = (tid & 1) * 16;
    const int vn = tid >> 3, vj = (tid & 7) * 4;

    for (int jt = 0; jt < 512; jt += 32) {
        __syncthreads();
        {
            const float* wr = &Wproj[(size_t)(ob + wo) * 8192 + jb + jt + wj];
#pragma unroll
            for (int u = 0; u < 4; u++) {
                float4 w = *(const float4*)&wr[u * 4];
                wT[(wj + u * 4 + 0) * 132 + wo] = w.x;
                wT[(wj + u * 4 + 1) * 132 + wo] = w.y;
                wT[(wj + u * 4 + 2) * 132 + wo] = w.z;
                wT[(wj + u * 4 + 3) * 132 + wo] = w.w;
            }
            float4 v = *(const float4*)&g_vlad[(size_t)vn * 8192 + jb + jt + vj];
            vT[(vj + 0) * 36 + vn] = v.x;
            vT[(vj + 1) * 36 + vn] = v.y;
            vT[(vj + 2) * 36 + vn] = v.z;
            vT[(vj + 3) * 36 + vn] = v.w;
        }
        __syncthreads();
#pragma unroll
        for (int j = 0; j < 32; j++) {
            float4 w0 = *(const float4*)&wT[j * 132 + og * 8];
            float4 w1 = *(const float4*)&wT[j * 132 + og * 8 + 4];
            unsigned long long vp = *(const unsigned long long*)&vT[j * 36 + ng * 2];
            unsigned long long wdr[8];
            DUP2(wdr[0], w0.x); DUP2(wdr[1], w0.y); DUP2(wdr[2], w0.z); DUP2(wdr[3], w0.w);
            DUP2(wdr[4], w1.x); DUP2(wdr[5], w1.y); DUP2(wdr[6], w1.z); DUP2(wdr[7], w1.w);
#pragma unroll
            for (int i = 0; i < 8; i++) FMA2(acc[i], wdr[i], vp);
        }
    }
#pragma unroll
    for (int i = 0; i < 8; i++) {
        float lo, hi;
        UNPK(lo, hi, acc[i]);
        int o = ob + og * 8 + i;
        atomicAdd(&g_proj[(ng * 2 + 0) * 1024 + o], lo);
        atomicAdd(&g_proj[(ng * 2 + 1) * 1024 + o], hi);
    }
}

// ---------------------------------------------------------------------------
__global__ void __launch_bounds__(256) kD(const float* __restrict__ bproj,
                                          float* __restrict__ out) {
    __shared__ float wr[8];
    __shared__ float inv_s;
    const int n = blockIdx.x, tid = threadIdx.x;
    float v[4]; float ps = 0.f;
#pragma unroll
    for (int r = 0; r < 4; r++) {
        int o = r * 256 + tid;
        v[r] = g_proj[n * 1024 + o] + bproj[o];
        ps += v[r] * v[r];
    }
#pragma unroll
    for (int off = 16; off; off >>= 1)
        ps += __shfl_xor_sync(0xffffffffu, ps, off);
    if ((tid & 31) == 0) wr[tid >> 5] = ps;
    __syncthreads();
    if (tid == 0) {
        float s = 0.f;
#pragma unroll
        for (int t = 0; t < 8; t++) s += wr[t];
        inv_s = 1.f / fmaxf(sqrtf(s), 1e-12f);
    }
    __syncthreads();
#pragma unroll
    for (int r = 0; r < 4; r++)
        out[n * 1024 + r * 256 + tid] = v[r] * inv_s;
}

// ---------------------------------------------------------------------------
extern "C" void kernel_launch(void* const* d_in, const int* in_sizes, int n_in,
                              void* d_out, int out_size) {
    const float* x         = (const float*)d_in[0];
    const float* Wpool     = (const float*)d_in[1];
    const float* bpool     = (const float*)d_in[2];
    const float* Wconv     = (const float*)d_in[3];
    const float* bconv     = (const float*)d_in[4];
    const float* centroids = (const float*)d_in[5];
    const float* Wproj     = (const float*)d_in[6];
    const float* bproj     = (const float*)d_in[7];
    float* out = (float*)d_out;

    cudaFuncSetAttribute(kA, cudaFuncAttributeMaxDynamicSharedMemorySize, 93184);

    kW<<<512, 256>>>(Wpool);
    kZ<<<1024, 256>>>();
    dim3 gA(13, 32);
    kA<<<gA, 256, 93184>>>(x, bpool, Wconv, bconv);
    dim3 gB(4, 32);
    kBfin<<<gB, 256>>>(centroids);
    dim3 gC(8, 16);
    kC<<<gC, 256>>>(Wproj);
    kD<<<32, 256>>>(bproj, out);
}

// round 12
// speedup vs baseline: 2.1273x; 1.4428x over previous
#include <cuda_runtime.h>
#include <cuda_fp16.h>
#include <cstdint>

// ---------------------------------------------------------------------------
// NetVLAD GB300 round 11: fp16 mma for pool GEMM *and* epilogue GEMMs
// (logits + vlad partial).  N=32, C=1024, D=128, K=64, S=784 (13 tiles of 64)
// ---------------------------------------------------------------------------

__device__ __align__(16) unsigned char g_wpk[589824];  // 16 chunks x 36864B W image
__device__ __align__(16) unsigned char g_wcpk[17408];  // Wconv fp16 [64 k][272B]
__device__ float g_vladraw[32 * 8192];
__device__ float g_vlad  [32 * 8192];
__device__ float g_sasum [32 * 64];
__device__ float g_proj  [32 * 1024];

#define FMA2(acc, a, b) \
    asm("fma.rn.f32x2 %0, %1, %2, %0;" : "+l"(acc) : "l"(a), "l"(b))
#define DUP2(d, s) \
    asm("mov.b64 %0, {%1, %1};" : "=l"(d) : "f"(s))
#define UNPK(lo, hi, s) \
    asm("mov.b64 {%0, %1}, %2;" : "=f"(lo), "=f"(hi) : "l"(s))

__device__ __forceinline__ uint32_t smem_u32(const void* p) {
    uint32_t a;
    asm("{ .reg .u64 t; cvta.to.shared.u64 t, %1; cvt.u32.u64 %0, t; }"
        : "=r"(a) : "l"(p));
    return a;
}
__device__ __forceinline__ void cpasync16(uint32_t smem, const void* gmem) {
    asm volatile("cp.async.cg.shared.global [%0], [%1], 16;"
        :: "r"(smem), "l"(gmem) : "memory");
}
#define CP_COMMIT() asm volatile("cp.async.commit_group;" ::: "memory")
#define CP_WAIT1()  asm volatile("cp.async.wait_group 1;" ::: "memory")

__device__ __forceinline__ void ldsm(unsigned* r, uint32_t a) {
    asm volatile("ldmatrix.sync.aligned.m8n8.x4.shared.b16 {%0,%1,%2,%3}, [%4];"
        : "=r"(r[0]), "=r"(r[1]), "=r"(r[2]), "=r"(r[3]) : "r"(a));
}
__device__ __forceinline__ void ldsmt(unsigned* r, uint32_t a) {
    asm volatile("ldmatrix.sync.aligned.m8n8.x4.trans.shared.b16 {%0,%1,%2,%3}, [%4];"
        : "=r"(r[0]), "=r"(r[1]), "=r"(r[2]), "=r"(r[3]) : "r"(a));
}
__device__ __forceinline__ void mma_f16(float* c, const unsigned* a, const unsigned* b) {
    asm volatile(
        "mma.sync.aligned.m16n8k16.row.col.f32.f16.f16.f32 "
        "{%0,%1,%2,%3}, {%4,%5,%6,%7}, {%8,%9}, {%0,%1,%2,%3};"
        : "+f"(c[0]), "+f"(c[1]), "+f"(c[2]), "+f"(c[3])
        : "r"(a[0]), "r"(a[1]), "r"(a[2]), "r"(a[3]), "r"(b[0]), "r"(b[1]));
}

// ---------------------------------------------------------------------------
__global__ void kW(const float* __restrict__ Wpool) {
    int idx = blockIdx.x * 256 + threadIdx.x;
    if (idx >= 131072) return;
    int d = idx >> 10, c = idx & 1023;
    float w = Wpool[idx];
    __half h = __float2half_rn(w);
    __half l = __float2half_rn(w - __half2float(h));
    int q = c >> 6, cl = c & 63;
    *(__half*)(g_wpk + q * 36864 + d * 144 + cl * 2) = h;
    *(__half*)(g_wpk + q * 36864 + 18432 + d * 144 + cl * 2) = l;
}

// kZ: zero accumulators + pack Wconv fp16 image [64 k][272B rows]
__global__ void kZ(const float* __restrict__ Wconv) {
    int idx = blockIdx.x * 256 + threadIdx.x;
    if (idx < 262144) g_vladraw[idx] = 0.f;
    if (idx < 2048)   g_sasum[idx] = 0.f;
    if (idx < 32768)  g_proj[idx] = 0.f;
    if (idx < 8192) {
        int k = idx >> 7, d = idx & 127;
        *(__half*)(g_wcpk + k * 272 + d * 2) = __float2half_rn(Wconv[idx]);
    }
}

// ---------------------------------------------------------------------------
// kA: fp16 2-term mma pool GEMM (128d x 64s) + fully-HMMA epilogue
// grid (13, 32), 256 thr, dyn smem 93184 B
// phase1: BUF(b) @ 1024 + b*46080: WH 18432 | WL 18432 | X 9216
// phase2 (bytes):
//   regionA @1024..35840: XF_A fp32 [128][68]  (dies)
//     then WcA fp16 [64][272] @1024 (dies) -> EP_log fp32 [64 s][68 k] @1024
//     saA fp16 [64 k][144] @18432
//   XF16_ds fp16 [128 d][144] @35840   (logits B)
//   XF16_sd fp16 [64 s][272] @54272    (vlad B)
//   EPinv [64]f @71680 | EPm [64][5]f @71936 | EPs2 [64][5]f @73216
// ---------------------------------------------------------------------------
__global__ void __launch_bounds__(256, 2) kA(const float* __restrict__ x,
                                             const float* __restrict__ bpool,
                                             const float* __restrict__ bconv) {
    extern __shared__ char smc[];
    float* smf = (float*)smc;
    const uint32_t sb = smem_u32(smc);

    const int tid = threadIdx.x, lane = tid & 31, wid = tid >> 5;
    const int n = blockIdx.y;
    const int s0 = blockIdx.x * 64;
    const bool fullv = (blockIdx.x < 12);

    const float* xn = x + (size_t)n * 1024 * 784;
    const int xc = tid >> 2, xs = (tid & 3) * 16;

    const int wd = wid & 3, ws = wid >> 2;
    const int md0 = wd * 32, ns0 = ws * 32;
    const int mat = lane >> 3, rr = lane & 7;
    const uint32_t aH0 = sb + 1024 + (uint32_t)(md0 + ((mat & 1) << 3) + rr) * 144
                         + ((uint32_t)(mat >> 1) << 4);
    const uint32_t bH0 = sb + 1024 + 36864 + (uint32_t)(((mat & 1) << 3) + rr) * 144
                         + (uint32_t)(ns0 + ((mat >> 1) << 3)) * 2;

    float acc[2][4][4];
#pragma unroll
    for (int mt = 0; mt < 2; mt++)
#pragma unroll
        for (int nf = 0; nf < 4; nf++)
#pragma unroll
            for (int u = 0; u < 4; u++) acc[mt][nf][u] = 0.f;

    float xr[16];

#define LOADX(q) do { \
    const float* p0 = xn + (size_t)((q) * 64 + xc) * 784 + s0 + xs; \
    if (fullv) { \
        _Pragma("unroll") \
        for (int u = 0; u < 4; u++) { \
            float4 a4 = ((const float4*)p0)[u]; \
            xr[u * 4] = a4.x; xr[u * 4 + 1] = a4.y; \
            xr[u * 4 + 2] = a4.z; xr[u * 4 + 3] = a4.w; \
        } \
    } else { \
        _Pragma("unroll") \
        for (int i = 0; i < 16; i++) \
            xr[i] = ((s0 + xs + i) < 784) ? p0[i] : 0.f; \
    } } while (0)

#define STOREX(b) do { \
    char* xh = smc + 1024 + (b) * 46080 + 36864 + xc * 144 + xs * 2; \
    _Pragma("unroll") \
    for (int i = 0; i < 8; i++) { \
        __half2 hp = __floats2half2_rn(xr[2 * i], xr[2 * i + 1]); \
        *(uint32_t*)(xh + i * 4) = *(uint32_t*)&hp; \
    } } while (0)

#define COPYW(q, b) do { \
    const unsigned char* src = g_wpk + (q) * 36864; \
    uint32_t dst = sb + 1024 + (b) * 46080; \
    _Pragma("unroll") \
    for (int i = 0; i < 9; i++) { \
        int seg = tid + i * 256; \
        cpasync16(dst + seg * 16, src + seg * 16); \
    } } while (0)

    LOADX(0);
    COPYW(0, 0); CP_COMMIT();
    COPYW(1, 1); CP_COMMIT();

    for (int q = 0; q < 16; q++) {
        const int b = q & 1;
        STOREX(b);
        if (q + 1 < 16) LOADX(q + 1);
        CP_WAIT1();
        __syncthreads();

        const uint32_t aH = aH0 + b * 46080;
        const uint32_t aL = aH + 18432;
        const uint32_t bH = bH0 + b * 46080;
#pragma unroll
        for (int ks = 0; ks < 4; ks++) {
            unsigned ah[2][4], al[2][4];
            ldsm(ah[0], aH + ks * 32);
            ldsm(ah[1], aH + ks * 32 + 2304);
            ldsm(al[0], aL + ks * 32);
            ldsm(al[1], aL + ks * 32 + 2304);
            unsigned bh[2][4];
#pragma unroll
            for (int nt = 0; nt < 2; nt++)
                ldsmt(bh[nt], bH + ks * 2304 + nt * 32);
#pragma unroll
            for (int mt = 0; mt < 2; mt++)
#pragma unroll
                for (int nf = 0; nf < 4; nf++) {
                    const unsigned* bhf = &bh[nf >> 1][(nf & 1) * 2];
                    mma_f16(acc[mt][nf], ah[mt], bhf);
                    mma_f16(acc[mt][nf], al[mt], bhf);
                }
        }
        __syncthreads();
        if (q + 2 < 16) COPYW(q + 2, b);
        CP_COMMIT();
    }
#undef LOADX
#undef STOREX
#undef COPYW

    const int r0w = lane >> 2, cq = lane & 3;

    // ---- acc -> XF_A[d][68 s] fp32 (+bias) ----
    {
#pragma unroll
        for (int mt = 0; mt < 2; mt++) {
            int d = md0 + mt * 16 + r0w;
            float b0 = __ldg(&bpool[d]);
            float b8 = __ldg(&bpool[d + 8]);
#pragma unroll
            for (int nf = 0; nf < 4; nf++) {
                int s = ns0 + nf * 8 + cq * 2;
                smf[256 + d * 68 + s]           = acc[mt][nf][0] + b0;
                smf[256 + d * 68 + s + 1]       = acc[mt][nf][1] + b0;
                smf[256 + (d + 8) * 68 + s]     = acc[mt][nf][2] + b8;
                smf[256 + (d + 8) * 68 + s + 1] = acc[mt][nf][3] + b8;
            }
        }
    }
    __syncthreads();

    // ---- column L2 norm over d -> EPinv @ float 17920 ----
    if (tid < 64) {
        float s = 0.f;
#pragma unroll 8
        for (int d = 0; d < 128; d++) {
            float v = smf[256 + d * 68 + tid];
            s += v * v;
        }
        smf[17920 + tid] = ((s0 + tid) < 784) ? 1.f / fmaxf(sqrtf(s), 1e-12f) : 0.f;
    }
    __syncthreads();

    // ---- build fp16 xf tiles: XF16_ds [d][144B] and XF16_sd [s][272B] ----
    {
        const int row = tid & 127, hs = tid >> 7;
#pragma unroll
        for (int g = 0; g < 8; g++) {
            int s4 = hs * 32 + g * 4;
            float4 v = *(const float4*)&smf[256 + row * 68 + s4];
            float4 m = *(const float4*)&smf[17920 + s4];
            v.x *= m.x; v.y *= m.y; v.z *= m.z; v.w *= m.w;
            __half2 h01 = __floats2half2_rn(v.x, v.y);
            __half2 h23 = __floats2half2_rn(v.z, v.w);
            *(uint32_t*)(smc + 35840 + row * 144 + s4 * 2)     = *(uint32_t*)&h01;
            *(uint32_t*)(smc + 35840 + row * 144 + s4 * 2 + 4) = *(uint32_t*)&h23;
            *(__half*)(smc + 54272 + (s4 + 0) * 272 + row * 2) = __low2half(h01);
            *(__half*)(smc + 54272 + (s4 + 1) * 272 + row * 2) = __high2half(h01);
            *(__half*)(smc + 54272 + (s4 + 2) * 272 + row * 2) = __low2half(h23);
            *(__half*)(smc + 54272 + (s4 + 3) * 272 + row * 2) = __high2half(h23);
        }
    }
    __syncthreads();

    // ---- copy Wconv fp16 image into regionA (XF_A dead) ----
    {
        const uint4* src = (const uint4*)g_wcpk;
        uint4* dst = (uint4*)(smc + 1024);
#pragma unroll
        for (int i = 0; i < 5; i++) {
            int seg = tid + i * 256;
            if (seg < 1088) dst[seg] = src[seg];
        }
    }
    __syncthreads();

    // ---- logits mma: M=64(k) N=64(s) K=128(d) ----
    float accl[4][4];
#pragma unroll
    for (int nf = 0; nf < 4; nf++)
#pragma unroll
        for (int u = 0; u < 4; u++) accl[nf][u] = 0.f;
    {
        const uint32_t aW = sb + 1024 + (uint32_t)(16 * wd + ((mat & 1) << 3) + rr) * 272
                            + ((uint32_t)(mat >> 1) << 4);
        const uint32_t bL = sb + 35840 + (uint32_t)(((mat & 1) << 3) + rr) * 144
                            + (uint32_t)(32 * ws + ((mat >> 1) << 3)) * 2;
#pragma unroll
        for (int ks = 0; ks < 8; ks++) {
            unsigned a[4];
            ldsm(a, aW + ks * 32);
            unsigned bb[2][4];
            ldsmt(bb[0], bL + ks * 2304);
            ldsmt(bb[1], bL + ks * 2304 + 32);
#pragma unroll
            for (int nf = 0; nf < 4; nf++)
                mma_f16(accl[nf], a, &bb[nf >> 1][(nf & 1) * 2]);
        }
    }
    __syncthreads();   // all mma done before EP_log overwrites WcA

    // ---- bias + store logits -> EP_log [s][68] fp32 @ float 256 ----
    {
        float bc0 = __ldg(&bconv[16 * wd + r0w]);
        float bc1 = __ldg(&bconv[16 * wd + r0w + 8]);
#pragma unroll
        for (int nf = 0; nf < 4; nf++) {
            int s = 32 * ws + nf * 8 + cq * 2;
            smf[256 + s * 68 + 16 * wd + r0w]           = accl[nf][0] + bc0;
            smf[256 + (s + 1) * 68 + 16 * wd + r0w]     = accl[nf][1] + bc0;
            smf[256 + s * 68 + 16 * wd + r0w + 8]       = accl[nf][2] + bc1;
            smf[256 + (s + 1) * 68 + 16 * wd + r0w + 8] = accl[nf][3] + bc1;
        }
    }
    __syncthreads();

    // ---- softmax over K=64 per s: thread = (s=tid&63, kg=tid>>6 of 16 k) ----
    {
        const int sidx = tid & 63, kg = tid >> 6;
        float lv[16];
        float mx = -1e30f;
#pragma unroll
        for (int i = 0; i < 16; i++) {
            lv[i] = smf[256 + sidx * 68 + kg * 16 + i];
            mx = fmaxf(mx, lv[i]);
        }
        smf[17984 + sidx * 5 + kg] = mx;
        __syncthreads();
        float M = fmaxf(fmaxf(smf[17984 + sidx * 5], smf[17984 + sidx * 5 + 1]),
                        fmaxf(smf[17984 + sidx * 5 + 2], smf[17984 + sidx * 5 + 3]));
        float es = 0.f;
#pragma unroll
        for (int i = 0; i < 16; i++) { lv[i] = __expf(lv[i] - M); es += lv[i]; }
        smf[18304 + sidx * 5 + kg] = es;
        __syncthreads();
        float tot = smf[18304 + sidx * 5] + smf[18304 + sidx * 5 + 1]
                  + smf[18304 + sidx * 5 + 2] + smf[18304 + sidx * 5 + 3];
        float r = ((s0 + sidx) < 784) ? 1.f / tot : 0.f;
#pragma unroll
        for (int i = 0; i < 16; i++)
            *(__half*)(smc + 18432 + (kg * 16 + i) * 144 + sidx * 2) =
                __float2half_rn(lv[i] * r);
    }
    __syncthreads();

    // ---- sasum from rounded sa ----
    if (tid < 64) {
        const __half2* rp = (const __half2*)(smc + 18432 + tid * 144);
        float s = 0.f;
#pragma unroll
        for (int i = 0; i < 32; i++) {
            float2 f = __half22float2(rp[i]);
            s += f.x + f.y;
        }
        atomicAdd(&g_sasum[n * 64 + tid], s);
    }

    // ---- vlad mma: M=64(k) N=128(d) K=64(s) -> atomicAdd g_vladraw ----
    {
        const uint32_t aV = sb + 18432 + (uint32_t)(16 * wd + ((mat & 1) << 3) + rr) * 144
                            + ((uint32_t)(mat >> 1) << 4);
        const uint32_t bV = sb + 54272 + (uint32_t)(((mat & 1) << 3) + rr) * 272
                            + (uint32_t)(64 * ws + ((mat >> 1) << 3)) * 2;
        float accv[8][4];
#pragma unroll
        for (int nf = 0; nf < 8; nf++)
#pragma unroll
            for (int u = 0; u < 4; u++) accv[nf][u] = 0.f;
#pragma unroll
        for (int ks = 0; ks < 4; ks++) {
            unsigned a[4];
            ldsm(a, aV + ks * 32);
            unsigned bb[4][4];
#pragma unroll
            for (int nt = 0; nt < 4; nt++)
                ldsmt(bb[nt], bV + ks * 4352 + nt * 32);
#pragma unroll
            for (int nf = 0; nf < 8; nf++)
                mma_f16(accv[nf], a, &bb[nf >> 1][(nf & 1) * 2]);
        }
        float* vr = g_vladraw + (size_t)n * 8192;
        const int k0 = 16 * wd + r0w, k1 = k0 + 8;
#pragma unroll
        for (int nf = 0; nf < 8; nf++) {
            int d = 64 * ws + nf * 8 + cq * 2;
            atomicAdd(&vr[k0 * 128 + d],     accv[nf][0]);
            atomicAdd(&vr[k0 * 128 + d + 1], accv[nf][1]);
            atomicAdd(&vr[k1 * 128 + d],     accv[nf][2]);
            atomicAdd(&vr[k1 * 128 + d + 1], accv[nf][3]);
        }
    }
}

// ---------------------------------------------------------------------------
// kBfin: vlad = vladraw - centroids*sasum, intra-norm over K
// ---------------------------------------------------------------------------
__global__ void __launch_bounds__(256) kBfin(const float* __restrict__ centroids) {
    __shared__ float ssm[64];
    __shared__ float red[8][33];
    const int dt = blockIdx.x, n = blockIdx.y, tid = threadIdx.x;
    const int dl = tid & 31, kg = tid >> 5;
    const int d = dt * 32 + dl;
    if (tid < 64) ssm[tid] = g_sasum[n * 64 + tid];
    __syncthreads();
    const float* vr = g_vladraw + (size_t)n * 8192;
    float v[8], sq = 0.f;
#pragma unroll
    for (int j = 0; j < 8; j++) {
        int k = kg * 8 + j;
        float val = vr[k * 128 + d] - centroids[k * 128 + d] * ssm[k];
        v[j] = val;
        sq += val * val;
    }
    red[kg][dl] = sq;
    __syncthreads();
    float tot = 0.f;
#pragma unroll
    for (int t = 0; t < 8; t++) tot += red[t][dl];
    float inv = 1.f / fmaxf(sqrtf(tot), 1e-12f);
    float* vo = g_vlad + (size_t)n * 8192;
#pragma unroll
    for (int j = 0; j < 8; j++)
        vo[(kg * 8 + j) * 128 + d] = v[j] * inv;
}

// ---------------------------------------------------------------------------
// kC: proj += vlad @ Wproj^T.  grid (8 o-tiles of 128, 16 j-splits of 512)
// ---------------------------------------------------------------------------
__global__ void __launch_bounds__(256) kC(const float* __restrict__ Wproj) {
    __shared__ float wT[32 * 132];
    __shared__ float vT[32 * 36];
    const int tid = threadIdx.x;
    const int ob = blockIdx.x * 128;
    const int jb = blockIdx.y * 512;
    const int og = tid >> 4;
    const int ng = tid & 15;

    unsigned long long acc[8];
#pragma unroll
    for (int i = 0; i < 8; i++) acc[i] = 0ull;

    const int wo = tid >> 1, wj = (tid & 1) * 16;
    const int vn = tid >> 3, vj = (tid & 7) * 4;

    for (int jt = 0; jt < 512; jt += 32) {
        __syncthreads();
        {
            const float* wr = &Wproj[(size_t)(ob + wo) * 8192 + jb + jt + wj];
#pragma unroll
            for (int u = 0; u < 4; u++) {
                float4 w = *(const float4*)&wr[u * 4];
                wT[(wj + u * 4 + 0) * 132 + wo] = w.x;
                wT[(wj + u * 4 + 1) * 132 + wo] = w.y;
                wT[(wj + u * 4 + 2) * 132 + wo] = w.z;
                wT[(wj + u * 4 + 3) * 132 + wo] = w.w;
            }
            float4 v = *(const float4*)&g_vlad[(size_t)vn * 8192 + jb + jt + vj];
            vT[(vj + 0) * 36 + vn] = v.x;
            vT[(vj + 1) * 36 + vn] = v.y;
            vT[(vj + 2) * 36 + vn] = v.z;
            vT[(vj + 3) * 36 + vn] = v.w;
        }
        __syncthreads();
#pragma unroll
        for (int j = 0; j < 32; j++) {
            float4 w0 = *(const float4*)&wT[j * 132 + og * 8];
            float4 w1 = *(const float4*)&wT[j * 132 + og * 8 + 4];
            unsigned long long vp = *(const unsigned long long*)&vT[j * 36 + ng * 2];
            unsigned long long wdr[8];
            DUP2(wdr[0], w0.x); DUP2(wdr[1], w0.y); DUP2(wdr[2], w0.z); DUP2(wdr[3], w0.w);
            DUP2(wdr[4], w1.x); DUP2(wdr[5], w1.y); DUP2(wdr[6], w1.z); DUP2(wdr[7], w1.w);
#pragma unroll
            for (int i = 0; i < 8; i++) FMA2(acc[i], wdr[i], vp);
        }
    }
#pragma unroll
    for (int i = 0; i < 8; i++) {
        float lo, hi;
        UNPK(lo, hi, acc[i]);
        int o = ob + og * 8 + i;
        atomicAdd(&g_proj[(ng * 2 + 0) * 1024 + o], lo);
        atomicAdd(&g_proj[(ng * 2 + 1) * 1024 + o], hi);
    }
}

// ---------------------------------------------------------------------------
__global__ void __launch_bounds__(256) kD(const float* __restrict__ bproj,
                                          float* __restrict__ out) {
    __shared__ float wr[8];
    __shared__ float inv_s;
    const int n = blockIdx.x, tid = threadIdx.x;
    float v[4]; float ps = 0.f;
#pragma unroll
    for (int r = 0; r < 4; r++) {
        int o = r * 256 + tid;
        v[r] = g_proj[n * 1024 + o] + bproj[o];
        ps += v[r] * v[r];
    }
#pragma unroll
    for (int off = 16; off; off >>= 1)
        ps += __shfl_xor_sync(0xffffffffu, ps, off);
    if ((tid & 31) == 0) wr[tid >> 5] = ps;
    __syncthreads();
    if (tid == 0) {
        float s = 0.f;
#pragma unroll
        for (int t = 0; t < 8; t++) s += wr[t];
        inv_s = 1.f / fmaxf(sqrtf(s), 1e-12f);
    }
    __syncthreads();
#pragma unroll
    for (int r = 0; r < 4; r++)
        out[n * 1024 + r * 256 + tid] = v[r] * inv_s;
}

// ---------------------------------------------------------------------------
extern "C" void kernel_launch(void* const* d_in, const int* in_sizes, int n_in,
                              void* d_out, int out_size) {
    const float* x         = (const float*)d_in[0];
    const float* Wpool     = (const float*)d_in[1];
    const float* bpool     = (const float*)d_in[2];
    const float* Wconv     = (const float*)d_in[3];
    const float* bconv     = (const float*)d_in[4];
    const float* centroids = (const float*)d_in[5];
    const float* Wproj     = (const float*)d_in[6];
    const float* bproj     = (const float*)d_in[7];
    float* out = (float*)d_out;

    cudaFuncSetAttribute(kA, cudaFuncAttributeMaxDynamicSharedMemorySize, 93184);

    kW<<<512, 256>>>(Wpool);
    kZ<<<1024, 256>>>(Wconv);
    dim3 gA(13, 32);
    kA<<<gA, 256, 93184>>>(x, bpool, bconv);
    dim3 gB(4, 32);
    kBfin<<<gB, 256>>>(centroids);
    dim3 gC(8, 16);
    kC<<<gC, 256>>>(Wproj);
    kD<<<32, 256>>>(bproj, out);
}